// round 11
// baseline (speedup 1.0000x reference)
#include <cuda_runtime.h>
#include <cstdint>

#define SEQ   512
#define BATCH 512
#define IDIM  300
#define HDIM  300
#define NP    320            // padded hidden for XP layout
#define JH    152            // per-CTA j-half in scan (2*152 = 304 >= 300)
#define MTOT  (SEQ*BATCH)

// GEMM tiling: 64x160 tile, 256 threads, 4m x 10n per thread
#define BM 64
#define BN 160
#define BK 20
#define GTH 256

// scan config: 456 threads = 76 j-pairs x 6 k-sixths; 8 batch per thread
#define STH   456
#define SKQ   6
#define SKCH  (IDIM/SKQ)          // 50
#define HB    (304*8)             // one h buffer: [304 j][8 b] floats
#define WSZ   (IDIM*JH)           // 45600 floats (W_hh half, k-major)
#define NPART ((SKQ-1)*8*76)      // 3040 u64 partials: [kq-1][slot][jp]

// -------- scratch (static device global; no allocations) --------
__device__ float g_XP[(long long)MTOT * NP];     // ~335 MB

// -------- f32x2 helpers (Blackwell packed fp32, PTX-only) --------
__device__ __forceinline__ unsigned long long bcast2(float v) {
    unsigned long long r;
    asm("mov.b64 %0, {%1, %1};" : "=l"(r) : "f"(v));
    return r;
}
__device__ __forceinline__ void ffma2(unsigned long long& d, unsigned long long a, unsigned long long b) {
    asm("fma.rn.f32x2 %0, %1, %2, %3;" : "=l"(d) : "l"(a), "l"(b), "l"(d));
}
__device__ __forceinline__ void fadd2(unsigned long long& d, unsigned long long a) {
    asm("add.rn.f32x2 %0, %1, %2;" : "=l"(d) : "l"(d), "l"(a));
}
__device__ __forceinline__ void unpack2(unsigned long long v, float& lo, float& hi) {
    asm("mov.b64 {%0, %1}, %2;" : "=f"(lo), "=f"(hi) : "l"(v));
}
__device__ __forceinline__ uint32_t smem_u32(const void* p) {
    uint32_t a;
    asm("{ .reg .u64 t; cvta.to.shared.u64 t, %1; cvt.u32.u64 %0, t; }" : "=r"(a) : "l"(p));
    return a;
}
// fast tanh: 1 - 2/(exp(2x)+1); saturates correctly at +-inf
__device__ __forceinline__ float fast_tanh(float x) {
    float e = __expf(2.0f * x);
    return 1.0f - __fdividef(2.0f, e + 1.0f);
}
__device__ __forceinline__ void dsmem_st64(uint32_t addr, unsigned peer, float lo, float hi) {
    asm volatile("{ .reg .b32 pa; .reg .b64 d; mov.b64 d, {%2,%3}; "
                 "mapa.shared::cluster.u32 pa, %0, %1; st.shared::cluster.b64 [pa], d; }"
                 :: "r"(addr), "r"(peer), "f"(lo), "f"(hi) : "memory");
}

// -------- x_proj GEMM: XP[m][j] = IN[m][:] . W_ih[j][:] + b_ih[j] + b_hh[j] --------
// launch_bounds(256, 2): 128-reg cap — 80 acc regs + temps FIT (the R8-R10
// (256,3)=85-reg cap forced accumulator spills to local memory every k-iter).
__global__ __launch_bounds__(GTH, 2) void gemm_xproj(const float* __restrict__ IN,
                                                     const float* __restrict__ Wih,
                                                     const float* __restrict__ bih,
                                                     const float* __restrict__ bhh,
                                                     int m_blk_off) {
    __shared__ float As[BK][BM + 4];  // [k][m], padded
    __shared__ float Bs[BK][BN];      // [k][n], n contiguous
    int tid = threadIdx.x;
    int m0 = (blockIdx.y + m_blk_off) * BM;
    int n0 = blockIdx.x * BN;
    int mth = tid >> 4, nth = tid & 15;   // 16 x 16
    int tm0 = mth * 4, tn0 = nth * 10;

    unsigned long long acc[4][5];
    #pragma unroll
    for (int i = 0; i < 4; i++)
        #pragma unroll
        for (int u = 0; u < 5; u++) acc[i][u] = 0ull;

    for (int kk = 0; kk < IDIM; kk += BK) {
        #pragma unroll
        for (int l = 0; l < (BM * BK) / GTH; l++) {
            int idx = tid + l * GTH;
            int m = idx / BK, k = idx % BK;
            As[k][m] = IN[(long long)(m0 + m) * IDIM + kk + k];
        }
        #pragma unroll
        for (int slot = tid; slot < BN * (BK / 4); slot += GTH) {
            int n = slot % BN, kg = slot / BN;
            int gn = n0 + n;
            float4 v = make_float4(0.f, 0.f, 0.f, 0.f);
            if (gn < HDIM)
                v = *(const float4*)&Wih[(long long)gn * IDIM + kk + kg * 4];
            Bs[kg * 4 + 0][n] = v.x;
            Bs[kg * 4 + 1][n] = v.y;
            Bs[kg * 4 + 2][n] = v.z;
            Bs[kg * 4 + 3][n] = v.w;
        }
        __syncthreads();
        #pragma unroll
        for (int k = 0; k < BK; k++) {
            float4 av = *(const float4*)&As[k][tm0];
            const unsigned long long* Bk = (const unsigned long long*)&Bs[k][tn0];
            unsigned long long b0 = Bk[0], b1 = Bk[1], b2 = Bk[2], b3 = Bk[3], b4 = Bk[4];
            unsigned long long a0 = bcast2(av.x), a1 = bcast2(av.y);
            unsigned long long a2 = bcast2(av.z), a3 = bcast2(av.w);
            ffma2(acc[0][0], a0, b0); ffma2(acc[0][1], a0, b1); ffma2(acc[0][2], a0, b2);
            ffma2(acc[0][3], a0, b3); ffma2(acc[0][4], a0, b4);
            ffma2(acc[1][0], a1, b0); ffma2(acc[1][1], a1, b1); ffma2(acc[1][2], a1, b2);
            ffma2(acc[1][3], a1, b3); ffma2(acc[1][4], a1, b4);
            ffma2(acc[2][0], a2, b0); ffma2(acc[2][1], a2, b1); ffma2(acc[2][2], a2, b2);
            ffma2(acc[2][3], a2, b3); ffma2(acc[2][4], a2, b4);
            ffma2(acc[3][0], a3, b0); ffma2(acc[3][1], a3, b1); ffma2(acc[3][2], a3, b2);
            ffma2(acc[3][3], a3, b3); ffma2(acc[3][4], a3, b4);
        }
        __syncthreads();
    }
    float bias[10];
    #pragma unroll
    for (int u = 0; u < 10; u++) {
        int gn = n0 + tn0 + u;
        bias[u] = (gn < HDIM) ? (bih[gn] + bhh[gn]) : 0.f;
    }
    #pragma unroll
    for (int i = 0; i < 4; i++) {
        long long row = (long long)(m0 + tm0 + i) * NP + n0 + tn0;
        #pragma unroll
        for (int u = 0; u < 5; u++) {
            float lo, hi; unpack2(acc[i][u], lo, hi);
            float2 v = make_float2(lo + bias[2 * u], hi + bias[2 * u + 1]);
            *(float2*)&g_XP[row + 2 * u] = v;
        }
    }
}

// -------- recurrent scan: 64 clusters x 2 CTAs, 8 batch per cluster --------
// 456 threads = (j-pair jp 0..75) x (k-sixth kq 0..5); thread: 2j x 8b x 50k.
// W_hh half in SMEM (k-major, [k][152]); inner loop per k: 1 LDS.64 (w pair)
// + 2 LDS.128 (h) + 8 FFMA2  -> FFMA2:LDS = 8:3, fma-bound (~2850 cyc floor)
// with 14.25 warps hiding. kq!=0 threads dump 8 acc u64 to PART; kq==0
// threads keep theirs in regs, reduce 5 partials each, fast_tanh 16 values,
// write h local (4x STS.128) + peer (8x DSMEM b64). mbarrier handshake/step.
__global__ __cluster_dims__(2, 1, 1) __launch_bounds__(STH, 1)
void scan_kernel(const float* __restrict__ Whh, float* __restrict__ out) {
    extern __shared__ float sm[];
    float* WT = sm;                                           // [300][152]
    float* H  = sm + WSZ;                                     // [2][304*8]
    unsigned long long* PART = (unsigned long long*)(H + 2 * HB);  // [5][8][76]
    unsigned long long* mbarp = PART + NPART;

    int tid = threadIdx.x;
    unsigned rank;
    asm("mov.u32 %0, %%cluster_ctarank;" : "=r"(rank));
    int cid = blockIdx.x >> 1;
    unsigned peer = rank ^ 1u;

    if (tid == 0) {
        asm volatile("mbarrier.init.shared.b64 [%0], 1;"
                     :: "r"(smem_u32(mbarp)) : "memory");
    }
    // WT[k][j] = Whh[rank*152+j][k] (global reads coalesced in k)
    for (int idx = tid; idx < JH * IDIM; idx += STH) {
        int j = idx / IDIM, k = idx % IDIM;
        int jg = rank * JH + j;
        WT[k * JH + j] = (jg < HDIM) ? Whh[(long long)jg * HDIM + k] : 0.f;
    }
    for (int i = tid; i < 2 * HB; i += STH) H[i] = 0.f;

    int kq = tid / 76, jp = tid % 76;
    int j0 = jp * 2;
    int jglob = rank * JH + j0;
    int kstart = kq * SKCH;
    bool base = (kq == 0);
    const float* Wp0 = WT + kstart * JH + j0;
    uint32_t hbase32 = smem_u32(H);
    uint32_t mbar32 = smem_u32(mbarp);
    const float* xpb = g_XP + (long long)(cid * 8) * NP + jglob;

    __syncthreads();
    asm volatile("barrier.cluster.arrive.aligned;" ::: "memory");
    asm volatile("barrier.cluster.wait.aligned;" ::: "memory");

    int p = 0;
    for (int t = 0; t < SEQ; t++) {
        // base threads prefetch xp (float2 = rows j0,j0+1) for 8 batches
        float2 xp[8];
        if (base) {
            const float* xr = xpb + (long long)t * BATCH * NP;
            #pragma unroll
            for (int b = 0; b < 8; b++) xp[b] = *(const float2*)(xr + b * NP);
        }

        // MAC over this thread's k-sixth
        unsigned long long A[8];
        #pragma unroll
        for (int s = 0; s < 8; s++) A[s] = 0ull;
        const float* Wp = Wp0;
        const float* hp = H + p * HB + kstart * 8;
        #pragma unroll 10
        for (int kk = 0; kk < SKCH; kk++) {
            float2 w = *(const float2*)(Wp + kk * JH);
            ulonglong2 hA = *(const ulonglong2*)(hp + kk * 8);
            ulonglong2 hB = *(const ulonglong2*)(hp + kk * 8 + 4);
            unsigned long long w0 = bcast2(w.x);
            unsigned long long w1 = bcast2(w.y);
            ffma2(A[0], w0, hA.x); ffma2(A[1], w0, hA.y);
            ffma2(A[2], w0, hB.x); ffma2(A[3], w0, hB.y);
            ffma2(A[4], w1, hA.x); ffma2(A[5], w1, hA.y);
            ffma2(A[6], w1, hB.x); ffma2(A[7], w1, hB.y);
        }
        if (!base) {
            unsigned long long* dst = PART + (kq - 1) * 8 * 76 + jp;
            #pragma unroll
            for (int s = 0; s < 8; s++) dst[s * 76] = A[s];
        }
        __syncthreads();

        if (base) {
            #pragma unroll
            for (int q = 0; q < SKQ - 1; q++) {
                const unsigned long long* src = PART + q * 8 * 76 + jp;
                #pragma unroll
                for (int s = 0; s < 8; s++) fadd2(A[s], src[s * 76]);
            }
            // rows j0 (A[0..3]) and j0+1 (A[4..7]); slot c = batch pair (2c,2c+1)
            float r0[8], r1[8];
            #pragma unroll
            for (int c = 0; c < 4; c++) {
                float lo, hi;
                unpack2(A[c], lo, hi);
                r0[2 * c]     = fast_tanh(xp[2 * c].x + lo);
                r0[2 * c + 1] = fast_tanh(xp[2 * c + 1].x + hi);
                unpack2(A[4 + c], lo, hi);
                r1[2 * c]     = fast_tanh(xp[2 * c].y + lo);
                r1[2 * c + 1] = fast_tanh(xp[2 * c + 1].y + hi);
            }
            int off0 = (1 - p) * HB + jglob * 8;   // row j0
            int off1 = off0 + 8;                   // row j0+1
            *(float4*)(H + off0)     = make_float4(r0[0], r0[1], r0[2], r0[3]);
            *(float4*)(H + off0 + 4) = make_float4(r0[4], r0[5], r0[6], r0[7]);
            *(float4*)(H + off1)     = make_float4(r1[0], r1[1], r1[2], r1[3]);
            *(float4*)(H + off1 + 4) = make_float4(r1[4], r1[5], r1[6], r1[7]);
            uint32_t ra0 = hbase32 + off0 * 4;
            uint32_t ra1 = hbase32 + off1 * 4;
            #pragma unroll
            for (int c = 0; c < 4; c++) {
                dsmem_st64(ra0 + c * 8u, peer, r0[2 * c], r0[2 * c + 1]);
                dsmem_st64(ra1 + c * 8u, peer, r1[2 * c], r1[2 * c + 1]);
            }
        }
        __syncthreads();   // h stores (local + DSMEM issue) ordered before arrive
        if (tid == 0) {
            asm volatile("{ .reg .b32 pa; mapa.shared::cluster.u32 pa, %0, %1; "
                         "mbarrier.arrive.release.cluster.shared::cluster.b64 _, [pa]; }"
                         :: "r"(mbar32), "r"(peer) : "memory");
        }
        {
            unsigned ph = (unsigned)(t & 1);
            uint32_t done;
            asm volatile("{ .reg .pred p; "
                         "mbarrier.try_wait.parity.acquire.cluster.shared::cta.b64 p, [%1], %2; "
                         "selp.b32 %0, 1, 0, p; }"
                         : "=r"(done) : "r"(mbar32), "r"(ph) : "memory");
            if (!done) {
                asm volatile("{ .reg .pred P1; "
                             "WL%=: mbarrier.try_wait.parity.acquire.cluster.shared::cta.b64 P1, [%0], %1, 0x989680; "
                             "@P1 bra.uni WD%=; bra.uni WL%=; WD%=: }"
                             :: "r"(mbar32), "r"(ph) : "memory");
            }
        }
        p ^= 1;
    }

    // write final h: each CTA writes its j-half for the cluster's 8 batches
    const float* Hf = H + p * HB;
    int cb0 = cid * 8;
    for (int idx = tid; idx < 8 * JH; idx += STH) {
        int b = idx / JH, jj = idx % JH;
        int j = rank * JH + jj;
        if (j < HDIM) out[(long long)(cb0 + b) * HDIM + j] = Hf[j * 8 + b];
    }
    asm volatile("barrier.cluster.arrive.aligned;" ::: "memory");
    asm volatile("barrier.cluster.wait.aligned;" ::: "memory");
}

extern "C" void kernel_launch(void* const* d_in, const int* in_sizes, int n_in,
                              void* d_out, int out_size) {
    const float* IN  = (const float*)d_in[0];
    const float* Wih = (const float*)d_in[1];
    const float* Whh = (const float*)d_in[2];
    const float* bih = (const float*)d_in[3];
    const float* bhh = (const float*)d_in[4];
    float* out = (float*)d_out;

    // gemm split into 3 launches -> 4-launch period puts the ncu capture
    // (6th launch, -s 5 -c 1) on a gemm chunk for direct spill verification.
    dim3 gA(NP / BN, 1366), gB(NP / BN, 1365), gC(NP / BN, 1365);
    gemm_xproj<<<gA, GTH>>>(IN, Wih, bih, bhh, 0);
    gemm_xproj<<<gB, GTH>>>(IN, Wih, bih, bhh, 1366);
    gemm_xproj<<<gC, GTH>>>(IN, Wih, bih, bhh, 2731);

    // smem: WT 182400 + H 19456 + PART 24320 + mbar 8 = 226184 B
    size_t smem = (size_t)WSZ * 4 + (size_t)2 * HB * 4 + (size_t)NPART * 8 + 8;
    cudaFuncSetAttribute(scan_kernel, cudaFuncAttributeMaxDynamicSharedMemorySize, (int)smem);
    scan_kernel<<<128, STH, smem>>>(Whh, out);
}

// round 12
// speedup vs baseline: 1.2430x; 1.2430x over previous
#include <cuda_runtime.h>
#include <cstdint>

#define SEQ   512
#define BATCH 512
#define IDIM  300
#define HDIM  300
#define NP    320            // padded hidden for XP layout
#define JH    152            // per-CTA j-half in scan
#define MTOT  (SEQ*BATCH)

// GEMM tiling: 64x160 tile, 256 threads, 4m x 10n per thread (40 acc regs)
#define BM 64
#define BN 160
#define BK 20
#define GTH 256

// scan: 608 threads = 4 k-quarters x (76 j-pairs x 2 halves); 2j x 4b x 76k each
#define STH    608
#define SKQ    4
#define SKCH   76                 // k rows per quarter (304 total, permuted)
#define KROWS  304
#define HB     (KROWS*8)          // one h buffer: [304 rows][8 b] floats
#define WSZ    (KROWS*JH)         // 46208 floats
#define PSTR   (STH+4)            // padded PART slot stride (u64) — bank shift

// -------- scratch (static device global; no allocations) --------
__device__ float g_XP[(long long)MTOT * NP];     // ~335 MB

// -------- f32x2 helpers (Blackwell packed fp32, PTX-only) --------
__device__ __forceinline__ unsigned long long bcast2(float v) {
    unsigned long long r;
    asm("mov.b64 %0, {%1, %1};" : "=l"(r) : "f"(v));
    return r;
}
__device__ __forceinline__ void ffma2(unsigned long long& d, unsigned long long a, unsigned long long b) {
    asm("fma.rn.f32x2 %0, %1, %2, %3;" : "=l"(d) : "l"(a), "l"(b), "l"(d));
}
__device__ __forceinline__ void fadd2(unsigned long long& d, unsigned long long a) {
    asm("add.rn.f32x2 %0, %1, %2;" : "=l"(d) : "l"(d), "l"(a));
}
__device__ __forceinline__ void unpack2(unsigned long long v, float& lo, float& hi) {
    asm("mov.b64 {%0, %1}, %2;" : "=f"(lo), "=f"(hi) : "l"(v));
}
__device__ __forceinline__ uint32_t smem_u32(const void* p) {
    uint32_t a;
    asm("{ .reg .u64 t; cvta.to.shared.u64 t, %1; cvt.u32.u64 %0, t; }" : "=r"(a) : "l"(p));
    return a;
}
// fast tanh: 1 - 2/(exp(2x)+1); saturates correctly at +-inf
__device__ __forceinline__ float fast_tanh(float x) {
    float e = __expf(2.0f * x);
    return 1.0f - __fdividef(2.0f, e + 1.0f);
}
__device__ __forceinline__ void dsmem_st64(uint32_t addr, unsigned peer, float lo, float hi) {
    asm volatile("{ .reg .b32 pa; .reg .b64 d; mov.b64 d, {%2,%3}; "
                 "mapa.shared::cluster.u32 pa, %0, %1; st.shared::cluster.b64 [pa], d; }"
                 :: "r"(addr), "r"(peer), "f"(lo), "f"(hi) : "memory");
}

// -------- x_proj GEMM: XP[m][j] = IN[m][:] . W_ih[j][:] + b_ih[j] + b_hh[j] --------
__global__ __launch_bounds__(GTH, 3) void gemm_xproj(const float* __restrict__ IN,
                                                     const float* __restrict__ Wih,
                                                     const float* __restrict__ bih,
                                                     const float* __restrict__ bhh) {
    __shared__ float As[BK][BM + 4];  // [k][m], padded
    __shared__ float Bs[BK][BN];      // [k][n], n contiguous
    int tid = threadIdx.x;
    int m0 = blockIdx.y * BM;
    int n0 = blockIdx.x * BN;
    int mth = tid >> 4, nth = tid & 15;   // 16 x 16
    int tm0 = mth * 4, tn0 = nth * 10;

    unsigned long long acc[4][5];
    #pragma unroll
    for (int i = 0; i < 4; i++)
        #pragma unroll
        for (int u = 0; u < 5; u++) acc[i][u] = 0ull;

    for (int kk = 0; kk < IDIM; kk += BK) {
        #pragma unroll
        for (int l = 0; l < (BM * BK) / GTH; l++) {
            int idx = tid + l * GTH;
            int m = idx / BK, k = idx % BK;
            As[k][m] = IN[(long long)(m0 + m) * IDIM + kk + k];
        }
        #pragma unroll
        for (int slot = tid; slot < BN * (BK / 4); slot += GTH) {
            int n = slot % BN, kg = slot / BN;
            int gn = n0 + n;
            float4 v = make_float4(0.f, 0.f, 0.f, 0.f);
            if (gn < HDIM)
                v = *(const float4*)&Wih[(long long)gn * IDIM + kk + kg * 4];
            Bs[kg * 4 + 0][n] = v.x;
            Bs[kg * 4 + 1][n] = v.y;
            Bs[kg * 4 + 2][n] = v.z;
            Bs[kg * 4 + 3][n] = v.w;
        }
        __syncthreads();
        #pragma unroll
        for (int k = 0; k < BK; k++) {
            float4 av = *(const float4*)&As[k][tm0];
            const unsigned long long* Bk = (const unsigned long long*)&Bs[k][tn0];
            unsigned long long b0 = Bk[0], b1 = Bk[1], b2 = Bk[2], b3 = Bk[3], b4 = Bk[4];
            unsigned long long a0 = bcast2(av.x), a1 = bcast2(av.y);
            unsigned long long a2 = bcast2(av.z), a3 = bcast2(av.w);
            ffma2(acc[0][0], a0, b0); ffma2(acc[0][1], a0, b1); ffma2(acc[0][2], a0, b2);
            ffma2(acc[0][3], a0, b3); ffma2(acc[0][4], a0, b4);
            ffma2(acc[1][0], a1, b0); ffma2(acc[1][1], a1, b1); ffma2(acc[1][2], a1, b2);
            ffma2(acc[1][3], a1, b3); ffma2(acc[1][4], a1, b4);
            ffma2(acc[2][0], a2, b0); ffma2(acc[2][1], a2, b1); ffma2(acc[2][2], a2, b2);
            ffma2(acc[2][3], a2, b3); ffma2(acc[2][4], a2, b4);
            ffma2(acc[3][0], a3, b0); ffma2(acc[3][1], a3, b1); ffma2(acc[3][2], a3, b2);
            ffma2(acc[3][3], a3, b3); ffma2(acc[3][4], a3, b4);
        }
        __syncthreads();
    }
    float bias[10];
    #pragma unroll
    for (int u = 0; u < 10; u++) {
        int gn = n0 + tn0 + u;
        bias[u] = (gn < HDIM) ? (bih[gn] + bhh[gn]) : 0.f;
    }
    #pragma unroll
    for (int i = 0; i < 4; i++) {
        long long row = (long long)(m0 + tm0 + i) * NP + n0 + tn0;
        #pragma unroll
        for (int u = 0; u < 5; u++) {
            float lo, hi; unpack2(acc[i][u], lo, hi);
            float2 v = make_float2(lo + bias[2 * u], hi + bias[2 * u + 1]);
            *(float2*)&g_XP[row + 2 * u] = v;
        }
    }
}

// -------- recurrent scan: 64 clusters x 2 CTAs, 8 batch per cluster --------
// Permuted-k layout: H rows [0,152) = OWN j-half h, rows [152,304) = PEER's
// (delivered by peer DSMEM stores); WT permuted to match. k-quarters 0-1 read
// only own rows -> their warps start each step's MAC without waiting; k-quarter
// 2-3 warps first wait on the peer's mbarrier arrive (overlapped with local MAC
// on the other warps). Per k-iter (warp): LDS.64 w (1 wf) + LDS.128 h (1 wf,
// half-pair window) + 2 bcast + 4 FFMA2 -> issue = fma = LDS = 2888 cyc floor.
// Tail: all 608 threads reduce ONE u64 output (4 LDS.64 + 3 fadd2 + 2 tanh +
// STS.64 + DSMEM st64), then sync + single release-arrive to peer.
__global__ __cluster_dims__(2, 1, 1) __launch_bounds__(STH, 1)
void scan_kernel(const float* __restrict__ Whh, float* __restrict__ out) {
    extern __shared__ float sm[];
    float* WT = sm;                                           // [304][152] permuted-k
    float* H  = sm + WSZ;                                     // [2][304][8]
    unsigned long long* PART = (unsigned long long*)(H + 2 * HB);  // [4][PSTR]
    unsigned long long* mbarp = PART + 4 * PSTR;

    int tid = threadIdx.x;
    unsigned rank;
    asm("mov.u32 %0, %%cluster_ctarank;" : "=r"(rank));
    int cid = blockIdx.x >> 1;
    unsigned peer = rank ^ 1u;

    if (tid == 0) {
        asm volatile("mbarrier.init.shared.b64 [%0], 1;"
                     :: "r"(smem_u32(mbarp)) : "memory");
    }
    // WT[kloc][j] = Whh[rank*152+j][kglob(kloc)] ; kloc<152 -> own k region,
    // kloc>=152 -> peer k region (coalesced over kglob)
    for (int idx = tid; idx < JH * KROWS; idx += STH) {
        int j = idx / KROWS, kloc = idx % KROWS;
        int jg = rank * JH + j;
        int kg = (kloc < JH) ? (rank * JH + kloc) : (peer * JH + (kloc - JH));
        float v = 0.f;
        if (jg < HDIM && kg < HDIM) v = Whh[(long long)jg * HDIM + kg];
        WT[kloc * JH + j] = v;
    }
    for (int i = tid; i < 2 * HB; i += STH) H[i] = 0.f;

    // MAC-role indices: tid = kq*152 + jp*2 + half
    int kq = tid / 152, lid2 = tid % 152;
    int jp = lid2 >> 1, half = lid2 & 1;
    int j0 = jp * 2;
    int kstart = kq * SKCH;
    const float* Wp0 = WT + kstart * JH + j0;
    bool remote_warp = (tid >> 5) >= 9;      // warps containing kq>=2 lanes

    // reduce-role indices: one u64 output (row j_out, batch pair bq)
    int j_out = tid >> 2, bq = tid & 3;
    int jglob_o = rank * JH + j_out;
    int lid2_s = (j_out >> 1) * 2 + (bq >> 1);   // producer lane within kq block
    int s_slot = (j_out & 1) * 2 + (bq & 1);     // producer acc slot
    bool xp_ok = (jglob_o < HDIM);
    const float* xpb = g_XP + (long long)(cid * 8 + bq * 2) * NP + jglob_o;

    uint32_t hbase32 = smem_u32(H);
    uint32_t mbar32 = smem_u32(mbarp);

    __syncthreads();
    asm volatile("barrier.cluster.arrive.aligned;" ::: "memory");
    asm volatile("barrier.cluster.wait.aligned;" ::: "memory");

    int p = 0;
    for (int t = 0; t < SEQ; t++) {
        // xp prefetch for this thread's output (hidden under MAC)
        float x0 = 0.f, x1 = 0.f;
        if (xp_ok) {
            const float* xr = xpb + (long long)t * BATCH * NP;
            x0 = xr[0];
            x1 = xr[NP];
        }
        // remote warps wait for peer's step-(t-1) h-half; local warps proceed
        if (t > 0 && remote_warp) {
            unsigned ph = (unsigned)((t - 1) & 1);
            uint32_t done;
            asm volatile("{ .reg .pred p; "
                         "mbarrier.try_wait.parity.acquire.cluster.shared::cta.b64 p, [%1], %2; "
                         "selp.b32 %0, 1, 0, p; }"
                         : "=r"(done) : "r"(mbar32), "r"(ph) : "memory");
            if (!done) {
                asm volatile("{ .reg .pred P1; "
                             "WL%=: mbarrier.try_wait.parity.acquire.cluster.shared::cta.b64 P1, [%0], %1, 0x989680; "
                             "@P1 bra.uni WD%=; bra.uni WL%=; WD%=: }"
                             :: "r"(mbar32), "r"(ph) : "memory");
            }
        }

        // MAC over this thread's k-quarter (2j x 4b x 76k)
        unsigned long long A00 = 0, A01 = 0, A10 = 0, A11 = 0;
        const float* Wp = Wp0;
        const float* hp = H + p * HB + kstart * 8 + half * 4;
        #pragma unroll 4
        for (int kk = 0; kk < SKCH; kk++) {
            float2 w = *(const float2*)(Wp + kk * JH);
            ulonglong2 hv = *(const ulonglong2*)(hp + kk * 8);
            unsigned long long w0 = bcast2(w.x);
            unsigned long long w1 = bcast2(w.y);
            ffma2(A00, w0, hv.x); ffma2(A01, w0, hv.y);
            ffma2(A10, w1, hv.x); ffma2(A11, w1, hv.y);
        }
        PART[0 * PSTR + tid] = A00;
        PART[1 * PSTR + tid] = A01;
        PART[2 * PSTR + tid] = A10;
        PART[3 * PSTR + tid] = A11;
        __syncthreads();

        // reduce 4 k-quarter partials for output (j_out, batches 2bq, 2bq+1)
        const unsigned long long* src = PART + s_slot * PSTR + lid2_s;
        unsigned long long acc = src[0];
        fadd2(acc, src[152]);
        fadd2(acc, src[304]);
        fadd2(acc, src[456]);
        float v0, v1;
        unpack2(acc, v0, v1);
        float h0 = fast_tanh(x0 + v0);
        float h1 = fast_tanh(x1 + v1);
        int off = (1 - p) * HB + j_out * 8 + bq * 2;          // own region row
        *(float2*)(H + off) = make_float2(h0, h1);
        uint32_t rdst = hbase32 + ((1 - p) * HB + (JH + j_out) * 8 + bq * 2) * 4;
        dsmem_st64(rdst, peer, h0, h1);                       // peer's [152+j] row

        __syncthreads();   // local H writes + DSMEM stores ordered before arrive
        if (tid == 0) {
            asm volatile("{ .reg .b32 pa; mapa.shared::cluster.u32 pa, %0, %1; "
                         "mbarrier.arrive.release.cluster.shared::cluster.b64 _, [pa]; }"
                         :: "r"(mbar32), "r"(peer) : "memory");
        }
        p ^= 1;
    }

    // final h: own rows [0,152) of H[p] -> out (no peer data needed)
    const float* Hf = H + p * HB;
    int cb0 = cid * 8;
    for (int idx = tid; idx < 8 * JH; idx += STH) {
        int b = idx / JH, jj = idx % JH;
        int j = rank * JH + jj;
        if (j < HDIM) out[(long long)(cb0 + b) * HDIM + j] = Hf[jj * 8 + b];
    }
    asm volatile("barrier.cluster.arrive.aligned;" ::: "memory");
    asm volatile("barrier.cluster.wait.aligned;" ::: "memory");
}

extern "C" void kernel_launch(void* const* d_in, const int* in_sizes, int n_in,
                              void* d_out, int out_size) {
    const float* IN  = (const float*)d_in[0];
    const float* Wih = (const float*)d_in[1];
    const float* Whh = (const float*)d_in[2];
    const float* bih = (const float*)d_in[3];
    const float* bhh = (const float*)d_in[4];
    float* out = (float*)d_out;

    dim3 g(NP / BN, MTOT / BM);   // (2, 4096)
    gemm_xproj<<<g, GTH>>>(IN, Wih, bih, bhh);

    // smem: WT 184832 + H 19456 + PART 19584 + mbar 8 = 223880 B
    size_t smem = (size_t)WSZ * 4 + (size_t)2 * HB * 4 + (size_t)4 * PSTR * 8 + 8;
    cudaFuncSetAttribute(scan_kernel, cudaFuncAttributeMaxDynamicSharedMemorySize, (int)smem);
    scan_kernel<<<128, STH, smem>>>(Whh, out);
}